// round 16
// baseline (speedup 1.0000x reference)
#include <cuda_runtime.h>
#include <cuda_bf16.h>
#include <cstdint>
#include <cstddef>

// ---------------------------------------------------------------------------
// Problem constants
// ---------------------------------------------------------------------------
#define V_SZ   32000
#define E_DIM  256
#define H_SZ   1024
#define BATCH  8
#define SEQ    512
#define ROWS   (BATCH*SEQ)          // 4096
#define LOGITS ((size_t)ROWS*V_SZ)  // 131072000

// ---------------------------------------------------------------------------
// Device scratch (static allocation — no cudaMalloc allowed)
// ---------------------------------------------------------------------------
__device__ float g_outs[(size_t)ROWS * H_SZ];   // h1 per step (tf32-rounded), row r=b*512+t
__device__ float g_h0buf[2][H_SZ * BATCH];      // [j*8+b] layout
__device__ float g_h1buf[2][H_SZ * BATCH];
__device__ unsigned          g_barc = 0;
__device__ volatile unsigned g_barg = 0;

// ---------------------------------------------------------------------------
// Small helpers
// ---------------------------------------------------------------------------
__device__ __forceinline__ float f2tf32(float x)
{
    uint32_t u;
    asm("cvt.rna.tf32.f32 %0, %1;" : "=r"(u) : "f"(x));
    return __uint_as_float(u);
}
__device__ __forceinline__ unsigned long long fma2(
    unsigned long long a, unsigned long long b, unsigned long long c)
{
    unsigned long long d;
    asm("fma.rn.f32x2 %0, %1, %2, %3;" : "=l"(d) : "l"(a), "l"(b), "l"(c));
    return d;
}
__device__ __forceinline__ unsigned long long pack2(float w)
{
    unsigned long long d;
    asm("mov.b64 %0, {%1, %1};" : "=l"(d) : "r"(__float_as_uint(w)));
    return d;
}
__device__ __forceinline__ void unpack2(unsigned long long v, float& lo, float& hi)
{
    uint32_t l, h;
    asm("mov.b64 {%0, %1}, %2;" : "=r"(l), "=r"(h) : "l"(v));
    lo = __uint_as_float(l); hi = __uint_as_float(h);
}
__device__ __forceinline__ void cp16(float* s, const float* g)
{
    unsigned sa = (unsigned)__cvta_generic_to_shared(s);
    asm volatile("cp.async.cg.shared.global [%0], [%1], 16;" :: "r"(sa), "l"(g));
}
#define CP_COMMIT() asm volatile("cp.async.commit_group;")
#define CP_WAIT0()  asm volatile("cp.async.wait_group 0;")
#define CP_WAIT1()  asm volatile("cp.async.wait_group 1;")
#define CP_WAIT2()  asm volatile("cp.async.wait_group 2;")

// ---------------------------------------------------------------------------
// Kernel 2: persistent pipelined recurrence with FUSED input-term GEMM.
//   Superstep s (0..512): H0(s+1)=tanh(e(s)@Wih0 + H0(s)W0 + b0)   [s<512]
//                         H1(s)  =tanh(H0(s)W1 + H1(s-1)W2 + b1)   [s>=1]
//   e(s) rows double-buffered in smem via cp.async (prefetched at s-1,
//   folded into chunk-0's commit group — group counts unchanged).
//   Flat central atomic barrier (proven fastest).
// ---------------------------------------------------------------------------
#define NCTA 128

__device__ __forceinline__ void grid_barrier()
{
    __syncthreads();
    __threadfence();
    if (threadIdx.x == 0) {
        unsigned gen = g_barg;
        unsigned a = atomicAdd(&g_barc, 1u);
        if (a == NCTA - 1) {
            g_barc = 0;
            __threadfence();
            g_barg = gen + 1;
        } else {
            while (g_barg == gen) { }
        }
    }
    __syncthreads();
}

__device__ __forceinline__ void rnn_stage(
    int c, float* sh0, float* sh1,
    const float* h0g, const float* h1g, int tid)
{
    const int off = c * 1024 + tid * 4;
    cp16(sh0 + off, h0g + off);
    cp16(sh1 + off, h1g + off);
}

// stage embedding rows for timestep s into se_buf ([b][256] raw layout):
// warp b stages emb[x[b*SEQ+s]][*] (1 KB) with 2 cp16 per thread.
__device__ __forceinline__ void stage_e(
    int s, float* se_buf, const int* __restrict__ x,
    const float* __restrict__ emb, int tid)
{
    const int b = tid >> 5;
    const int c = tid & 31;
    int tok = __ldg(x + b * SEQ + s);
    const float* src = emb + (size_t)tok * E_DIM + c * 8;
    float* dst = se_buf + b * E_DIM + c * 8;
    cp16(dst, src);
    cp16(dst + 4, src + 4);
}

// SMEM (floats): sh0[8192] sh1[8192] sred[1024] sb[8] sb0[8]
//                se[2][2048]  = 21520 floats = 86,080 B
#define RNN_SMEM_FLOATS 21520
#define RNN_SMEM_BYTES  (RNN_SMEM_FLOATS * 4)

__global__ void __launch_bounds__(256, 1) k_rnn(
    const int* __restrict__ x, const float* __restrict__ emb,
    const float* __restrict__ Wih0, const float* __restrict__ bih0,
    const float* __restrict__ bhh0,
    const float* __restrict__ Whh0, const float* __restrict__ Wih1,
    const float* __restrict__ Whh1, const float* __restrict__ bih1,
    const float* __restrict__ bhh1)
{
    extern __shared__ float sm[];
    float* sh0  = sm;
    float* sh1  = sm + 8192;
    float* sred = sm + 16384;   // 1024 (two sets of 512)
    float* sb   = sm + 17408;   // 8  (bih1+bhh1)
    float* sb0  = sm + 17416;   // 8  (bih0+bhh0)
    float* se   = sm + 17424;   // 2 x 2048

    const int tid  = threadIdx.x;
    const int j0   = blockIdx.x * 8;
    const int jl   = tid & 7;
    const int kg   = tid >> 3;       // 0..31
    const int lane = tid & 31;
    const int warp = tid >> 5;

    // initial embedding prefetch for s=0 (drained before the first barrier)
    stage_e(0, se, x, emb, tid);
    CP_COMMIT();

    // hidden-state weight slices into REGISTERS: Wr[i] = W[kg+32i][j0+jl]
    float W0r[32], W1r[32], W2r[32];
#pragma unroll
    for (int i = 0; i < 32; i++) {
        size_t off = (size_t)(kg + 32 * i) * H_SZ + j0 + jl;
        W0r[i] = Whh0[off];
        W1r[i] = Wih1[off];
        W2r[i] = Whh1[off];
    }
    // input weight slice (K=256): Wi0r[i] = Wih0[kg+32i][j0+jl], i<8
    float Wi0r[8];
#pragma unroll
    for (int i = 0; i < 8; i++)
        Wi0r[i] = Wih0[(size_t)(kg + 32 * i) * H_SZ + j0 + jl];

    if (tid < 8) {
        sb[tid]  = bih1[j0 + tid] + bhh1[j0 + tid];
        sb0[tid] = bih0[j0 + tid] + bhh0[j0 + tid];
    }

    if (tid < 64) {
        int o = blockIdx.x * 64 + tid;
        __stcg(&g_h0buf[0][o], 0.f); __stcg(&g_h0buf[1][o], 0.f);
        __stcg(&g_h1buf[0][o], 0.f); __stcg(&g_h1buf[1][o], 0.f);
    }
    CP_WAIT0();          // e(0) resident before anyone proceeds
    grid_barrier();

    for (int s = 0; s <= SEQ; s++) {
        const float* h0g = g_h0buf[s & 1];
        const float* h1g = g_h1buf[(s + 1) & 1];

        // prefetch e(s+1) into the other buffer; joins chunk-0's group below
        if (s + 1 < SEQ)
            stage_e(s + 1, se + ((s + 1) & 1) * 2048, x, emb, tid);
        rnn_stage(0, sh0, sh1, h0g, h1g, tid); CP_COMMIT();
        rnn_stage(1, sh0, sh1, h0g, h1g, tid); CP_COMMIT();

        // fused input-term GEMM: ea[b] = sum_i Wi0r[i] * e(s)[b][kg+32i]
        // (overlaps the chunk-0/1 arrival window)
        float ea[8];
#pragma unroll
        for (int b = 0; b < 8; b++) ea[b] = 0.f;
        {
            const float* e = se + (s & 1) * 2048;
#pragma unroll
            for (int i = 0; i < 8; i++) {
                const float w = Wi0r[i];
                const int k = kg + (i << 5);
#pragma unroll
                for (int b = 0; b < 8; b++)
                    ea[b] = fmaf(w, e[b * E_DIM + k], ea[b]);
            }
        }

        unsigned long long c0[4] = {0ull, 0ull, 0ull, 0ull};
        unsigned long long c1[4] = {0ull, 0ull, 0ull, 0ull};
#pragma unroll
        for (int c = 0; c < 8; c++) {
            if (c + 2 < 8) rnn_stage(c + 2, sh0, sh1, h0g, h1g, tid);
            CP_COMMIT();
            CP_WAIT2();
            __syncthreads();
#pragma unroll
            for (int ii = 0; ii < 4; ii++) {
                const int i = c * 4 + ii;
                const int k = kg + (i << 5);
                unsigned long long W0 = pack2(W0r[i]);
                unsigned long long W1 = pack2(W1r[i]);
                unsigned long long W2 = pack2(W2r[i]);
                const ulonglong2* hp = (const ulonglong2*)(sh0 + k * 8);
                const ulonglong2* hq = (const ulonglong2*)(sh1 + k * 8);
                ulonglong2 p0 = hp[0], p1 = hp[1];
                ulonglong2 q0 = hq[0], q1 = hq[1];
                c0[0] = fma2(W0, p0.x, c0[0]); c0[1] = fma2(W0, p0.y, c0[1]);
                c0[2] = fma2(W0, p1.x, c0[2]); c0[3] = fma2(W0, p1.y, c0[3]);
                c1[0] = fma2(W1, p0.x, c1[0]); c1[1] = fma2(W1, p0.y, c1[1]);
                c1[2] = fma2(W1, p1.x, c1[2]); c1[3] = fma2(W1, p1.y, c1[3]);
                c1[0] = fma2(W2, q0.x, c1[0]); c1[1] = fma2(W2, q0.y, c1[1]);
                c1[2] = fma2(W2, q1.x, c1[2]); c1[3] = fma2(W2, q1.y, c1[3]);
            }
        }
        float a0[8], a1[8];
#pragma unroll
        for (int q = 0; q < 4; q++) {
            unpack2(c0[q], a0[q * 2], a0[q * 2 + 1]);
            unpack2(c1[q], a1[q * 2], a1[q * 2 + 1]);
        }
        // add fused input-term partials (same kg partitioning -> same reduce)
#pragma unroll
        for (int q = 0; q < 8; q++) a0[q] += ea[q];
#pragma unroll
        for (int q = 0; q < 8; q++) {
            a0[q] += __shfl_xor_sync(0xffffffffu, a0[q], 8);
            a0[q] += __shfl_xor_sync(0xffffffffu, a0[q], 16);
            a1[q] += __shfl_xor_sync(0xffffffffu, a1[q], 8);
            a1[q] += __shfl_xor_sync(0xffffffffu, a1[q], 16);
        }
        if (lane < 8) {
#pragma unroll
            for (int b = 0; b < 8; b++) {
                sred[warp * 64 + lane * 8 + b]       = a0[b];
                sred[512 + warp * 64 + lane * 8 + b] = a1[b];
            }
        }
        __syncthreads();

        if (tid < 128) {
            const int set = tid >> 6;
            const int o   = tid & 63;
            const int b   = o >> 3, jj = o & 7;
            float v = 0.f;
#pragma unroll
            for (int w = 0; w < 8; w++) v += sred[set * 512 + w * 64 + jj * 8 + b];
            if (set == 0) {
                if (s < SEQ) {
                    float h = tanhf(v + sb0[jj]);
                    __stcg(&g_h0buf[(s + 1) & 1][(j0 + jj) * 8 + b], h);
                }
            } else {
                if (s >= 1) {
                    float h = tanhf(v + sb[jj]);
                    __stcg(&g_h1buf[s & 1][(j0 + jj) * 8 + b], h);
                    g_outs[((size_t)b * SEQ + (s - 1)) * H_SZ + j0 + jj] = f2tf32(h);
                }
            }
        }
        if (s < SEQ) grid_barrier();
    }
}

// ---------------------------------------------------------------------------
// Kernel 3: output projection  logits = g_outs @ W_out + b_out
//   (EXACT proven R15 version: 128x128x32, 128 thr, 2 CTAs/SM, NSTAGE=3,
//    one sync per k-tile, conflict-free strides, B direct from W_out,
//    fragment double-buffering.)
// ---------------------------------------------------------------------------
#define TM 128
#define TN 128
#define TK 32
#define SA_STRIDE 36
#define SB_STRIDE 136
#define SA_FLOATS (TM * SA_STRIDE)   // 4608
#define SB_FLOATS (TK * SB_STRIDE)   // 4352
#define NSTAGE 3
#define GEMM_THREADS 128
#define GEMM_SMEM_BYTES (NSTAGE * (SA_FLOATS + SB_FLOATS) * 4)  // 107520

__device__ __forceinline__ void gemm_stage(
    int kt, float* sA, float* sB, const float* __restrict__ Wout,
    int m0, int n0, int tid)
{
    const int k0 = kt * TK;
    const int ar = tid >> 3, ac = (tid & 7) * 4;    // ar 0..15
#pragma unroll
    for (int i = 0; i < 8; i++)
        cp16(sA + (ar + i * 16) * SA_STRIDE + ac,
             g_outs + (size_t)(m0 + ar + i * 16) * H_SZ + k0 + ac);
    const int br = tid >> 5, bc = (tid & 31) * 4;   // br 0..3
#pragma unroll
    for (int i = 0; i < 8; i++)
        cp16(sB + (br + i * 4) * SB_STRIDE + bc,
             Wout + (size_t)(k0 + br + i * 4) * V_SZ + n0 + bc);
}

__device__ __forceinline__ void load_frags(
    const float* A, const float* B, int kk,
    int wm, int wn, int g, int tg,
    uint32_t af[4][4], uint32_t bf[8][2])
{
    const int k8 = kk * 8;
#pragma unroll
    for (int mt = 0; mt < 4; mt++) {
        int r = wm * 64 + mt * 16 + g;
        af[mt][0] = __float_as_uint(A[r * SA_STRIDE + k8 + tg]);
        af[mt][1] = __float_as_uint(A[(r + 8) * SA_STRIDE + k8 + tg]);
        af[mt][2] = __float_as_uint(A[r * SA_STRIDE + k8 + tg + 4]);
        af[mt][3] = __float_as_uint(A[(r + 8) * SA_STRIDE + k8 + tg + 4]);
    }
#pragma unroll
    for (int nt = 0; nt < 8; nt++) {
        int c = wn * 64 + nt * 8 + g;
        bf[nt][0] = __float_as_uint(B[(k8 + tg) * SB_STRIDE + c]);
        bf[nt][1] = __float_as_uint(B[(k8 + tg + 4) * SB_STRIDE + c]);
    }
}

__device__ __forceinline__ void issue_mma(
    const uint32_t af[4][4], const uint32_t bf[8][2], float acc[4][8][4])
{
#pragma unroll
    for (int mt = 0; mt < 4; mt++)
#pragma unroll
        for (int nt = 0; nt < 8; nt++) {
            asm volatile(
                "mma.sync.aligned.m16n8k8.row.col.f32.tf32.tf32.f32 "
                "{%0,%1,%2,%3},{%4,%5,%6,%7},{%8,%9},{%0,%1,%2,%3};\n"
                : "+f"(acc[mt][nt][0]), "+f"(acc[mt][nt][1]),
                  "+f"(acc[mt][nt][2]), "+f"(acc[mt][nt][3])
                : "r"(af[mt][0]), "r"(af[mt][1]), "r"(af[mt][2]), "r"(af[mt][3]),
                  "r"(bf[nt][0]), "r"(bf[nt][1]));
        }
}

__global__ void __launch_bounds__(GEMM_THREADS, 2) k_out_gemm(
    const float* __restrict__ Wout, const float* __restrict__ bout,
    float* __restrict__ out)
{
    extern __shared__ float sm3[];
    float* sA = sm3;                          // NSTAGE x 4608
    float* sB = sm3 + NSTAGE * SA_FLOATS;     // NSTAGE x 4352

    const int tid  = threadIdx.x;
    const int m0   = blockIdx.x * TM;   // m-fast: B tiles reused via L2
    const int n0   = blockIdx.y * TN;
    const int warp = tid >> 5;          // 0..3
    const int lane = tid & 31;
    const int g    = lane >> 2;
    const int tg   = lane & 3;
    const int wm   = warp & 1;   // 2 warps along M (64 rows each)
    const int wn   = warp >> 1;  // 2 warps along N (64 cols each)

    float acc[4][8][4];
#pragma unroll
    for (int mt = 0; mt < 4; mt++)
#pragma unroll
        for (int nt = 0; nt < 8; nt++)
#pragma unroll
            for (int q = 0; q < 4; q++) acc[mt][nt][q] = 0.f;

    // prologue: stages 0 and 1 into slots 0, 1
    gemm_stage(0, sA, sB, Wout, m0, n0, tid);
    CP_COMMIT();
    gemm_stage(1, sA + SA_FLOATS, sB + SB_FLOATS, Wout, m0, n0, tid);
    CP_COMMIT();

    uint32_t afA[4][4], bfA[8][2];   // fragment buffer A (even kk)
    uint32_t afB[4][4], bfB[8][2];   // fragment buffer B (odd kk)

    for (int kt = 0; kt < 32; kt++) {
        CP_WAIT1();          // stage kt landed (kt+1 may still be in flight)
        __syncthreads();     // cross-thread visibility; frees slot (kt+2)%3

        const int buf = kt % NSTAGE;
        const float* A = sA + buf * SA_FLOATS;
        const float* B = sB + buf * SB_FLOATS;

        // software-pipelined fragments: load kk+1 while mma's of kk execute
        load_frags(A, B, 0, wm, wn, g, tg, afA, bfA);
        load_frags(A, B, 1, wm, wn, g, tg, afB, bfB);
        issue_mma(afA, bfA, acc);                       // kk=0
        load_frags(A, B, 2, wm, wn, g, tg, afA, bfA);
        issue_mma(afB, bfB, acc);                       // kk=1
        load_frags(A, B, 3, wm, wn, g, tg, afB, bfB);
        issue_mma(afA, bfA, acc);                       // kk=2
        issue_mma(afB, bfB, acc);                       // kk=3

        // issue stage kt+2 into slot (kt+2)%3 — distinct from slots kt%3 and
        // (kt+1)%3 that any warp may still be computing on.
        if (kt + 2 < 32) {
            int st = (kt + 2) % NSTAGE;
            gemm_stage(kt + 2, sA + st * SA_FLOATS, sB + st * SB_FLOATS,
                       Wout, m0, n0, tid);
        }
        CP_COMMIT();         // unconditional: keeps group count stable
    }

    // epilogue: bias + store
#pragma unroll
    for (int nt = 0; nt < 8; nt++) {
        int c = n0 + wn * 64 + nt * 8 + 2 * tg;
        float b0 = bout[c], b1 = bout[c + 1];
#pragma unroll
        for (int mt = 0; mt < 4; mt++) {
            int r = m0 + wm * 64 + mt * 16 + g;
            float2 v0 = make_float2(acc[mt][nt][0] + b0, acc[mt][nt][1] + b1);
            float2 v1 = make_float2(acc[mt][nt][2] + b0, acc[mt][nt][3] + b1);
            *(float2*)(out + (size_t)r * V_SZ + c) = v0;
            *(float2*)(out + (size_t)(r + 8) * V_SZ + c) = v1;
        }
    }
}

// ---------------------------------------------------------------------------
// Kernel 4: final hidden states h0, h1 (both end in buffer 0 after 512 steps)
// ---------------------------------------------------------------------------
__global__ void __launch_bounds__(256) k_tail(float* __restrict__ out)
{
    int idx = blockIdx.x * 256 + threadIdx.x;
    if (idx < BATCH * H_SZ) {
        int b = idx >> 10, j = idx & 1023;
        out[LOGITS + idx]                = g_h0buf[0][j * 8 + b];
        out[LOGITS + BATCH * H_SZ + idx] = g_h1buf[0][j * 8 + b];
    }
}

// ---------------------------------------------------------------------------
// Launch
// ---------------------------------------------------------------------------
extern "C" void kernel_launch(void* const* d_in, const int* in_sizes, int n_in,
                              void* d_out, int out_size)
{
    const int*   x     = (const int*)  d_in[0];
    const float* emb   = (const float*)d_in[1];
    const float* W_ih0 = (const float*)d_in[2];
    const float* b_ih0 = (const float*)d_in[3];
    const float* W_hh0 = (const float*)d_in[4];
    const float* b_hh0 = (const float*)d_in[5];
    const float* W_ih1 = (const float*)d_in[6];
    const float* b_ih1 = (const float*)d_in[7];
    const float* W_hh1 = (const float*)d_in[8];
    const float* b_hh1 = (const float*)d_in[9];
    const float* W_out = (const float*)d_in[10];
    const float* b_out = (const float*)d_in[11];
    float* out = (float*)d_out;

    cudaFuncSetAttribute(k_rnn, cudaFuncAttributeMaxDynamicSharedMemorySize,
                         RNN_SMEM_BYTES);
    cudaFuncSetAttribute(k_out_gemm, cudaFuncAttributeMaxDynamicSharedMemorySize,
                         GEMM_SMEM_BYTES);

    // 1) fused embed + persistent recurrence (128 co-resident CTAs)
    k_rnn<<<NCTA, 256, RNN_SMEM_BYTES>>>(x, emb, W_ih0, b_ih0, b_hh0,
                                         W_hh0, W_ih1, W_hh1, b_ih1, b_hh1);

    // 2) output projection: grid (m=32 fast, n=250), 128 thr, 2 CTAs/SM
    k_out_gemm<<<dim3(32, 250), GEMM_THREADS, GEMM_SMEM_BYTES>>>(W_out, b_out, out);

    // 3) final hidden states
    k_tail<<<32, 256>>>(out);
}

// round 17
// speedup vs baseline: 1.1218x; 1.1218x over previous
#include <cuda_runtime.h>
#include <cuda_bf16.h>
#include <cstdint>
#include <cstddef>

// ---------------------------------------------------------------------------
// Problem constants
// ---------------------------------------------------------------------------
#define V_SZ   32000
#define E_DIM  256
#define H_SZ   1024
#define BATCH  8
#define SEQ    512
#define ROWS   (BATCH*SEQ)          // 4096
#define LOGITS ((size_t)ROWS*V_SZ)  // 131072000

// ---------------------------------------------------------------------------
// Device scratch (static allocation — no cudaMalloc allowed)
// ---------------------------------------------------------------------------
__device__ float g_a0[(size_t)ROWS * H_SZ];     // input term [t*8+b][h]
__device__ float g_outs[(size_t)ROWS * H_SZ];   // h1 per step (tf32-rounded), row r=b*512+t
__device__ float g_h0buf[2][H_SZ * BATCH];      // [j*8+b] layout
__device__ float g_h1buf[2][H_SZ * BATCH];
__device__ unsigned          g_barc = 0;
__device__ volatile unsigned g_barg = 0;

// ---------------------------------------------------------------------------
// Small helpers
// ---------------------------------------------------------------------------
__device__ __forceinline__ float f2tf32(float x)
{
    uint32_t u;
    asm("cvt.rna.tf32.f32 %0, %1;" : "=r"(u) : "f"(x));
    return __uint_as_float(u);
}
__device__ __forceinline__ unsigned long long fma2(
    unsigned long long a, unsigned long long b, unsigned long long c)
{
    unsigned long long d;
    asm("fma.rn.f32x2 %0, %1, %2, %3;" : "=l"(d) : "l"(a), "l"(b), "l"(c));
    return d;
}
__device__ __forceinline__ unsigned long long pack2(float w)
{
    unsigned long long d;
    asm("mov.b64 %0, {%1, %1};" : "=l"(d) : "r"(__float_as_uint(w)));
    return d;
}
__device__ __forceinline__ void unpack2(unsigned long long v, float& lo, float& hi)
{
    uint32_t l, h;
    asm("mov.b64 {%0, %1}, %2;" : "=r"(l), "=r"(h) : "l"(v));
    lo = __uint_as_float(l); hi = __uint_as_float(h);
}
__device__ __forceinline__ void cp16(float* s, const float* g)
{
    unsigned sa = (unsigned)__cvta_generic_to_shared(s);
    asm volatile("cp.async.cg.shared.global [%0], [%1], 16;" :: "r"(sa), "l"(g));
}
#define CP_COMMIT() asm volatile("cp.async.commit_group;")
#define CP_WAIT1()  asm volatile("cp.async.wait_group 1;")
#define CP_WAIT2()  asm volatile("cp.async.wait_group 2;")

// ---------------------------------------------------------------------------
// Kernel 1: embedding gather + input GEMM  (proven R15 version)
// ---------------------------------------------------------------------------
__global__ void __launch_bounds__(256) k_embed_gemm(
    const int* __restrict__ x, const float* __restrict__ emb,
    const float* __restrict__ Wih0, const float* __restrict__ bih0,
    const float* __restrict__ bhh0)
{
    __shared__ float sA[64][68];
    __shared__ float sB[64][68];
    const int n0 = blockIdx.x * 64;
    const int m0 = blockIdx.y * 64;
    const int tid = threadIdx.x;
    const int ty = tid >> 4, tx = tid & 15;

    float acc[4][4];
#pragma unroll
    for (int i = 0; i < 4; i++)
#pragma unroll
        for (int j = 0; j < 4; j++) acc[i][j] = 0.f;

    for (int k0 = 0; k0 < E_DIM; k0 += 64) {
#pragma unroll
        for (int i = 0; i < 4; i++) {
            int r  = (tid >> 4) + i * 16;
            int c4 = tid & 15;
            int rg = m0 + r;
            int t  = rg >> 3, b = rg & 7;
            int tok = x[b * SEQ + t];
            float4 v = *(const float4*)(emb + (size_t)tok * E_DIM + k0 + c4 * 4);
            *(float4*)&sA[r][c4 * 4] = v;
        }
#pragma unroll
        for (int i = 0; i < 4; i++) {
            int kr = (tid >> 4) + i * 16;
            int c4 = tid & 15;
            float4 v = *(const float4*)(Wih0 + (size_t)(k0 + kr) * H_SZ + n0 + c4 * 4);
            *(float4*)&sB[kr][c4 * 4] = v;
        }
        __syncthreads();
#pragma unroll 8
        for (int k = 0; k < 64; k++) {
            float a[4], bb[4];
#pragma unroll
            for (int i = 0; i < 4; i++) a[i] = sA[ty * 4 + i][k];
#pragma unroll
            for (int j = 0; j < 4; j++) bb[j] = sB[k][tx * 4 + j];
#pragma unroll
            for (int i = 0; i < 4; i++)
#pragma unroll
                for (int j = 0; j < 4; j++) acc[i][j] += a[i] * bb[j];
        }
        __syncthreads();
    }
#pragma unroll
    for (int i = 0; i < 4; i++) {
        int r = m0 + ty * 4 + i;
#pragma unroll
        for (int j = 0; j < 4; j++) {
            int n = n0 + tx * 4 + j;
            g_a0[(size_t)r * H_SZ + n] = acc[i][j] + bih0[n] + bhh0[n];
        }
    }
}

// ---------------------------------------------------------------------------
// Kernel 2: persistent pipelined recurrence (proven R15 body).
//   DELTA: h-vector streaming 8 chunks -> 4 chunks (2048 floats each),
//   halving per-superstep CP_WAIT/sync rounds. Same wait-depth-2 pipeline,
//   same k coverage per chunk, math order bit-identical.
// ---------------------------------------------------------------------------
#define NCTA 128

__device__ __forceinline__ void grid_barrier()
{
    __syncthreads();
    __threadfence();
    if (threadIdx.x == 0) {
        unsigned gen = g_barg;
        unsigned a = atomicAdd(&g_barc, 1u);
        if (a == NCTA - 1) {
            g_barc = 0;
            __threadfence();
            g_barg = gen + 1;
        } else {
            while (g_barg == gen) { }
        }
    }
    __syncthreads();
}

// stage chunk c: floats [2048c, 2048c+2048) of both h vectors into smem
__device__ __forceinline__ void rnn_stage(
    int c, float* sh0, float* sh1,
    const float* h0g, const float* h1g, int tid)
{
    const int off = c * 2048 + tid * 4;
    cp16(sh0 + off,        h0g + off);
    cp16(sh0 + off + 1024, h0g + off + 1024);
    cp16(sh1 + off,        h1g + off);
    cp16(sh1 + off + 1024, h1g + off + 1024);
}

#define RNN_SMEM_FLOATS 17416
#define RNN_SMEM_BYTES  (RNN_SMEM_FLOATS * 4)

__global__ void __launch_bounds__(256, 1) k_rnn(
    const float* __restrict__ Whh0, const float* __restrict__ Wih1,
    const float* __restrict__ Whh1, const float* __restrict__ bih1,
    const float* __restrict__ bhh1)
{
    extern __shared__ float sm[];
    float* sh0  = sm;
    float* sh1  = sm + 8192;
    float* sred = sm + 16384;   // 1024 (two sets of 512)
    float* sb   = sm + 17408;   // 8

    const int tid  = threadIdx.x;
    const int j0   = blockIdx.x * 8;
    const int jl   = tid & 7;
    const int kg   = tid >> 3;       // 0..31
    const int lane = tid & 31;
    const int warp = tid >> 5;

    float W0r[32], W1r[32], W2r[32];
#pragma unroll
    for (int i = 0; i < 32; i++) {
        size_t off = (size_t)(kg + 32 * i) * H_SZ + j0 + jl;
        W0r[i] = Whh0[off];
        W1r[i] = Wih1[off];
        W2r[i] = Whh1[off];
    }
    if (tid < 8) sb[tid] = bih1[j0 + tid] + bhh1[j0 + tid];

    if (tid < 64) {
        int o = blockIdx.x * 64 + tid;
        __stcg(&g_h0buf[0][o], 0.f); __stcg(&g_h0buf[1][o], 0.f);
        __stcg(&g_h1buf[0][o], 0.f); __stcg(&g_h1buf[1][o], 0.f);
    }
    grid_barrier();

    for (int s = 0; s <= SEQ; s++) {
        const float* h0g = g_h0buf[s & 1];
        const float* h1g = g_h1buf[(s + 1) & 1];

        rnn_stage(0, sh0, sh1, h0g, h1g, tid); CP_COMMIT();
        rnn_stage(1, sh0, sh1, h0g, h1g, tid); CP_COMMIT();

        float a0v = 0.f;
        if (tid < 64 && s < SEQ) {
            int b = tid >> 3, jj = tid & 7;
            a0v = __ldcg(&g_a0[((size_t)s * 8 + b) * H_SZ + j0 + jj]);
        }

        unsigned long long c0[4] = {0ull, 0ull, 0ull, 0ull};
        unsigned long long c1[4] = {0ull, 0ull, 0ull, 0ull};
#pragma unroll
        for (int c = 0; c < 4; c++) {
            if (c + 2 < 4) rnn_stage(c + 2, sh0, sh1, h0g, h1g, tid);
            CP_COMMIT();          // unconditional: keeps group count stable
            CP_WAIT2();           // chunk c resident (c+1, c+2 in flight)
            __syncthreads();      // cross-thread visibility of cp.async data
#pragma unroll
            for (int ii = 0; ii < 8; ii++) {
                const int i = c * 8 + ii;
                const int k = kg + (i << 5);
                unsigned long long W0 = pack2(W0r[i]);
                unsigned long long W1 = pack2(W1r[i]);
                unsigned long long W2 = pack2(W2r[i]);
                const ulonglong2* hp = (const ulonglong2*)(sh0 + k * 8);
                const ulonglong2* hq = (const ulonglong2*)(sh1 + k * 8);
                ulonglong2 p0 = hp[0], p1 = hp[1];
                ulonglong2 q0 = hq[0], q1 = hq[1];
                c0[0] = fma2(W0, p0.x, c0[0]); c0[1] = fma2(W0, p0.y, c0[1]);
                c0[2] = fma2(W0, p1.x, c0[2]); c0[3] = fma2(W0, p1.y, c0[3]);
                c1[0] = fma2(W1, p0.x, c1[0]); c1[1] = fma2(W1, p0.y, c1[1]);
                c1[2] = fma2(W1, p1.x, c1[2]); c1[3] = fma2(W1, p1.y, c1[3]);
                c1[0] = fma2(W2, q0.x, c1[0]); c1[1] = fma2(W2, q0.y, c1[1]);
                c1[2] = fma2(W2, q1.x, c1[2]); c1[3] = fma2(W2, q1.y, c1[3]);
            }
        }
        float a0[8], a1[8];
#pragma unroll
        for (int q = 0; q < 4; q++) {
            unpack2(c0[q], a0[q * 2], a0[q * 2 + 1]);
            unpack2(c1[q], a1[q * 2], a1[q * 2 + 1]);
        }
#pragma unroll
        for (int q = 0; q < 8; q++) {
            a0[q] += __shfl_xor_sync(0xffffffffu, a0[q], 8);
            a0[q] += __shfl_xor_sync(0xffffffffu, a0[q], 16);
            a1[q] += __shfl_xor_sync(0xffffffffu, a1[q], 8);
            a1[q] += __shfl_xor_sync(0xffffffffu, a1[q], 16);
        }
        if (lane < 8) {
#pragma unroll
            for (int b = 0; b < 8; b++) {
                sred[warp * 64 + lane * 8 + b]       = a0[b];
                sred[512 + warp * 64 + lane * 8 + b] = a1[b];
            }
        }
        __syncthreads();

        if (tid < 128) {
            const int set = tid >> 6;
            const int o   = tid & 63;
            const int b   = o >> 3, jj = o & 7;
            float v = 0.f;
#pragma unroll
            for (int w = 0; w < 8; w++) v += sred[set * 512 + w * 64 + jj * 8 + b];
            if (set == 0) {
                if (s < SEQ) {
                    float h = tanhf(v + a0v);
                    __stcg(&g_h0buf[(s + 1) & 1][(j0 + jj) * 8 + b], h);
                }
            } else {
                if (s >= 1) {
                    float h = tanhf(v + sb[jj]);
                    __stcg(&g_h1buf[s & 1][(j0 + jj) * 8 + b], h);
                    g_outs[((size_t)b * SEQ + (s - 1)) * H_SZ + j0 + jj] = f2tf32(h);
                }
            }
        }
        if (s < SEQ) grid_barrier();
    }
}

// ---------------------------------------------------------------------------
// Kernel 3: output projection  logits = g_outs @ W_out + b_out
//   (EXACT proven R15 version: 128x128x32, 128 thr, 2 CTAs/SM, NSTAGE=3,
//    one sync per k-tile, conflict-free strides, B direct from W_out,
//    fragment double-buffering.)
// ---------------------------------------------------------------------------
#define TM 128
#define TN 128
#define TK 32
#define SA_STRIDE 36
#define SB_STRIDE 136
#define SA_FLOATS (TM * SA_STRIDE)   // 4608
#define SB_FLOATS (TK * SB_STRIDE)   // 4352
#define NSTAGE 3
#define GEMM_THREADS 128
#define GEMM_SMEM_BYTES (NSTAGE * (SA_FLOATS + SB_FLOATS) * 4)  // 107520

__device__ __forceinline__ void gemm_stage(
    int kt, float* sA, float* sB, const float* __restrict__ Wout,
    int m0, int n0, int tid)
{
    const int k0 = kt * TK;
    const int ar = tid >> 3, ac = (tid & 7) * 4;    // ar 0..15
#pragma unroll
    for (int i = 0; i < 8; i++)
        cp16(sA + (ar + i * 16) * SA_STRIDE + ac,
             g_outs + (size_t)(m0 + ar + i * 16) * H_SZ + k0 + ac);
    const int br = tid >> 5, bc = (tid & 31) * 4;   // br 0..3
#pragma unroll
    for (int i = 0; i < 8; i++)
        cp16(sB + (br + i * 4) * SB_STRIDE + bc,
             Wout + (size_t)(k0 + br + i * 4) * V_SZ + n0 + bc);
}

__device__ __forceinline__ void load_frags(
    const float* A, const float* B, int kk,
    int wm, int wn, int g, int tg,
    uint32_t af[4][4], uint32_t bf[8][2])
{
    const int k8 = kk * 8;
#pragma unroll
    for (int mt = 0; mt < 4; mt++) {
        int r = wm * 64 + mt * 16 + g;
        af[mt][0] = __float_as_uint(A[r * SA_STRIDE + k8 + tg]);
        af[mt][1] = __float_as_uint(A[(r + 8) * SA_STRIDE + k8 + tg]);
        af[mt][2] = __float_as_uint(A[r * SA_STRIDE + k8 + tg + 4]);
        af[mt][3] = __float_as_uint(A[(r + 8) * SA_STRIDE + k8 + tg + 4]);
    }
#pragma unroll
    for (int nt = 0; nt < 8; nt++) {
        int c = wn * 64 + nt * 8 + g;
        bf[nt][0] = __float_as_uint(B[(k8 + tg) * SB_STRIDE + c]);
        bf[nt][1] = __float_as_uint(B[(k8 + tg + 4) * SB_STRIDE + c]);
    }
}

__device__ __forceinline__ void issue_mma(
    const uint32_t af[4][4], const uint32_t bf[8][2], float acc[4][8][4])
{
#pragma unroll
    for (int mt = 0; mt < 4; mt++)
#pragma unroll
        for (int nt = 0; nt < 8; nt++) {
            asm volatile(
                "mma.sync.aligned.m16n8k8.row.col.f32.tf32.tf32.f32 "
                "{%0,%1,%2,%3},{%4,%5,%6,%7},{%8,%9},{%0,%1,%2,%3};\n"
                : "+f"(acc[mt][nt][0]), "+f"(acc[mt][nt][1]),
                  "+f"(acc[mt][nt][2]), "+f"(acc[mt][nt][3])
                : "r"(af[mt][0]), "r"(af[mt][1]), "r"(af[mt][2]), "r"(af[mt][3]),
                  "r"(bf[nt][0]), "r"(bf[nt][1]));
        }
}

__global__ void __launch_bounds__(GEMM_THREADS, 2) k_out_gemm(
    const float* __restrict__ Wout, const float* __restrict__ bout,
    float* __restrict__ out)
{
    extern __shared__ float sm3[];
    float* sA = sm3;                          // NSTAGE x 4608
    float* sB = sm3 + NSTAGE * SA_FLOATS;     // NSTAGE x 4352

    const int tid  = threadIdx.x;
    const int m0   = blockIdx.x * TM;   // m-fast: B tiles reused via L2
    const int n0   = blockIdx.y * TN;
    const int warp = tid >> 5;          // 0..3
    const int lane = tid & 31;
    const int g    = lane >> 2;
    const int tg   = lane & 3;
    const int wm   = warp & 1;   // 2 warps along M (64 rows each)
    const int wn   = warp >> 1;  // 2 warps along N (64 cols each)

    float acc[4][8][4];
#pragma unroll
    for (int mt = 0; mt < 4; mt++)
#pragma unroll
        for (int nt = 0; nt < 8; nt++)
#pragma unroll
            for (int q = 0; q < 4; q++) acc[mt][nt][q] = 0.f;

    // prologue: stages 0 and 1 into slots 0, 1
    gemm_stage(0, sA, sB, Wout, m0, n0, tid);
    CP_COMMIT();
    gemm_stage(1, sA + SA_FLOATS, sB + SB_FLOATS, Wout, m0, n0, tid);
    CP_COMMIT();

    uint32_t afA[4][4], bfA[8][2];   // fragment buffer A (even kk)
    uint32_t afB[4][4], bfB[8][2];   // fragment buffer B (odd kk)

    for (int kt = 0; kt < 32; kt++) {
        CP_WAIT1();          // stage kt landed (kt+1 may still be in flight)
        __syncthreads();     // cross-thread visibility; frees slot (kt+2)%3

        const int buf = kt % NSTAGE;
        const float* A = sA + buf * SA_FLOATS;
        const float* B = sB + buf * SB_FLOATS;

        // software-pipelined fragments: load kk+1 while mma's of kk execute
        load_frags(A, B, 0, wm, wn, g, tg, afA, bfA);
        load_frags(A, B, 1, wm, wn, g, tg, afB, bfB);
        issue_mma(afA, bfA, acc);                       // kk=0
        load_frags(A, B, 2, wm, wn, g, tg, afA, bfA);
        issue_mma(afB, bfB, acc);                       // kk=1
        load_frags(A, B, 3, wm, wn, g, tg, afB, bfB);
        issue_mma(afA, bfA, acc);                       // kk=2
        issue_mma(afB, bfB, acc);                       // kk=3

        // issue stage kt+2 into slot (kt+2)%3 — distinct from slots kt%3 and
        // (kt+1)%3 that any warp may still be computing on.
        if (kt + 2 < 32) {
            int st = (kt + 2) % NSTAGE;
            gemm_stage(kt + 2, sA + st * SA_FLOATS, sB + st * SB_FLOATS,
                       Wout, m0, n0, tid);
        }
        CP_COMMIT();         // unconditional: keeps group count stable
    }

    // epilogue: bias + store
#pragma unroll
    for (int nt = 0; nt < 8; nt++) {
        int c = n0 + wn * 64 + nt * 8 + 2 * tg;
        float b0 = bout[c], b1 = bout[c + 1];
#pragma unroll
        for (int mt = 0; mt < 4; mt++) {
            int r = m0 + wm * 64 + mt * 16 + g;
            float2 v0 = make_float2(acc[mt][nt][0] + b0, acc[mt][nt][1] + b1);
            float2 v1 = make_float2(acc[mt][nt][2] + b0, acc[mt][nt][3] + b1);
            *(float2*)(out + (size_t)r * V_SZ + c) = v0;
            *(float2*)(out + (size_t)(r + 8) * V_SZ + c) = v1;
        }
    }
}

// ---------------------------------------------------------------------------
// Kernel 4: final hidden states h0, h1 (both end in buffer 0 after 512 steps)
// ---------------------------------------------------------------------------
__global__ void __launch_bounds__(256) k_tail(float* __restrict__ out)
{
    int idx = blockIdx.x * 256 + threadIdx.x;
    if (idx < BATCH * H_SZ) {
        int b = idx >> 10, j = idx & 1023;
        out[LOGITS + idx]                = g_h0buf[0][j * 8 + b];
        out[LOGITS + BATCH * H_SZ + idx] = g_h1buf[0][j * 8 + b];
    }
}

// ---------------------------------------------------------------------------
// Launch
// ---------------------------------------------------------------------------
extern "C" void kernel_launch(void* const* d_in, const int* in_sizes, int n_in,
                              void* d_out, int out_size)
{
    const int*   x     = (const int*)  d_in[0];
    const float* emb   = (const float*)d_in[1];
    const float* W_ih0 = (const float*)d_in[2];
    const float* b_ih0 = (const float*)d_in[3];
    const float* W_hh0 = (const float*)d_in[4];
    const float* b_hh0 = (const float*)d_in[5];
    const float* W_ih1 = (const float*)d_in[6];
    const float* b_ih1 = (const float*)d_in[7];
    const float* W_hh1 = (const float*)d_in[8];
    const float* b_hh1 = (const float*)d_in[9];
    const float* W_out = (const float*)d_in[10];
    const float* b_out = (const float*)d_in[11];
    float* out = (float*)d_out;

    cudaFuncSetAttribute(k_rnn, cudaFuncAttributeMaxDynamicSharedMemorySize,
                         RNN_SMEM_BYTES);
    cudaFuncSetAttribute(k_out_gemm, cudaFuncAttributeMaxDynamicSharedMemorySize,
                         GEMM_SMEM_BYTES);

    // 1) input-term GEMM (separate, proven — R16 fusion rejected)
    k_embed_gemm<<<dim3(16, 64), 256>>>(x, emb, W_ih0, b_ih0, b_hh0);

    // 2) pipelined persistent recurrence (128 co-resident CTAs)
    k_rnn<<<NCTA, 256, RNN_SMEM_BYTES>>>(W_hh0, W_ih1, W_hh1, b_ih1, b_hh1);

    // 3) output projection: grid (m=32 fast, n=250), 128 thr, 2 CTAs/SM
    k_out_gemm<<<dim3(32, 250), GEMM_THREADS, GEMM_SMEM_BYTES>>>(W_out, b_out, out);

    // 4) final hidden states
    k_tail<<<32, 256>>>(out);
}